// round 14
// baseline (speedup 1.0000x reference)
#include <cuda_runtime.h>
#include <cstdint>
#include <math.h>

#define SEQ 2048
#define DH  64
#define BQ  64
#define BK  64
#define NT  (SEQ/BK)
#define SCALEF 0.03125f

#define ST_Q 68
#define ST_P 68
#define ST_K 68
#define ST_V 72

// smem float offsets
#define F_MSK 0                       // 64 (per-tile mask)
#define F_LSB 64                      // 128 (lsum halves)
#define F_QS  192                     // 64 x 68
#define F_P   (F_QS + BQ*ST_Q)       // 4544 (also epilogue scratch)
#define F_KS  (F_P  + BQ*ST_P)       // 8896
#define F_VS  (F_KS + BK*ST_K)       // 13248
#define SMEM_FLOATS (F_VS + BK*ST_V) // 17856
#define SMEM_BYTES  (SMEM_FLOATS*4)  // 71424 -> 3 CTAs/SM

static __device__ __forceinline__ uint32_t f2t(float x){
    uint32_t r; asm("cvt.rna.tf32.f32 %0, %1;" : "=r"(r) : "f"(x)); return r;
}
static __device__ __forceinline__ void mma8(float c[4], const uint32_t a[4],
                                            uint32_t b0, uint32_t b1){
    asm volatile("mma.sync.aligned.m16n8k8.row.col.f32.tf32.tf32.f32 "
        "{%0,%1,%2,%3}, {%4,%5,%6,%7}, {%8,%9}, {%0,%1,%2,%3};"
        : "+f"(c[0]),"+f"(c[1]),"+f"(c[2]),"+f"(c[3])
        : "r"(a[0]),"r"(a[1]),"r"(a[2]),"r"(a[3]), "r"(b0),"r"(b1));
}

__global__ __launch_bounds__(256,3)
void attn_mma4_kernel(const float* __restrict__ Q, const float* __restrict__ K,
                      const float* __restrict__ V, const int* __restrict__ mask,
                      float* __restrict__ O)
{
    extern __shared__ float sm[];
    uint32_t* usm = (uint32_t*)sm;
    const int tid  = threadIdx.x;
    const int wid  = tid >> 5, lane = tid & 31;
    const int gid  = lane >> 2, tig = lane & 3;
    const int wg   = wid & 3;              // row group (16 rows)
    const int hw   = wid >> 2;             // column half (0: cols 0-31, 1: 32-63)
    const int rA   = wg*16 + gid, rB = rA + 8;

    const int qt = blockIdx.x, bh = blockIdx.y, b = bh >> 4;
    const float* Qg = Q + ((size_t)bh*SEQ + (size_t)qt*BQ)*DH;
    const float* Kg = K + (size_t)bh*SEQ*DH;
    const float* Vg = V + (size_t)bh*SEQ*DH;
    const int*   Mg = mask + (size_t)b*SEQ;
    float*       Og = O + ((size_t)bh*SEQ + (size_t)qt*BQ)*DH;

    // ---- stage Q as tf32, row-major stride 68, STS.128 ----
    {
        const float4* Qg4 = (const float4*)Qg;
        #pragma unroll
        for (int p = 0; p < 4; ++p){
            int f = tid + p*256;
            float4 q4 = Qg4[f];
            int row = f >> 4, c4 = (f & 15) * 4;
            uint4 u = { f2t(q4.x), f2t(q4.y), f2t(q4.z), f2t(q4.w) };
            *(uint4*)(usm + F_QS + row*ST_Q + c4) = u;
        }
    }

    // ---- prefetch tile 0 K/V + mask ----
    float4 kreg[4], vreg[4];
    int mreg;
    {
        const float4* Kg4 = (const float4*)Kg;
        const float4* Vg4 = (const float4*)Vg;
        #pragma unroll
        for (int p=0;p<4;++p){ kreg[p]=Kg4[tid+p*256]; vreg[p]=Vg4[tid+p*256]; }
        mreg = (tid < BK) ? Mg[tid] : 0;
    }

    float o[8][4];
    float lsum0 = 0.f, lsum1 = 0.f;
    #pragma unroll
    for (int j=0;j<8;++j){ o[j][0]=o[j][1]=o[j][2]=o[j][3]=0.f; }

    for (int kt = 0; kt < NT; ++kt){
        if (kt) __syncthreads();    // prev PV done reading Ks/Vs; softmax done with msk

        // ---- stage K (stride 68) / V (stride 72) / mask ----
        #pragma unroll
        for (int p=0;p<4;++p){
            int f = tid + p*256;
            int row = f >> 4, c4 = (f & 15) * 4;
            uint4 ku = { f2t(kreg[p].x), f2t(kreg[p].y), f2t(kreg[p].z), f2t(kreg[p].w) };
            uint4 vu = { f2t(vreg[p].x), f2t(vreg[p].y), f2t(vreg[p].z), f2t(vreg[p].w) };
            *(uint4*)(usm + F_KS + row*ST_K + c4) = ku;
            *(uint4*)(usm + F_VS + row*ST_V + c4) = vu;
        }
        if (tid < BK) sm[F_MSK + tid] = (float)mreg;
        __syncthreads();

        // ---- S = Q K^T : this warp's 4 j-tiles (cols 32*hw .. +31) ----
        float s_[4][4];
        #pragma unroll
        for (int j=0;j<4;++j){ s_[j][0]=s_[j][1]=s_[j][2]=s_[j][3]=0.f; }
        #pragma unroll
        for (int s=0;s<8;++s){
            uint32_t qa[4];
            const uint32_t* qb = usm + F_QS + rA*ST_Q + 8*s + tig;
            qa[0]=qb[0]; qa[1]=qb[8*ST_Q]; qa[2]=qb[4]; qa[3]=qb[8*ST_Q+4];
            #pragma unroll
            for (int j=0;j<4;++j){
                const uint32_t* kb = usm + F_KS + (8*(4*hw+j)+gid)*ST_K + 8*s + tig;
                mma8(s_[j], qa, kb[0], kb[4]);
            }
        }

        // ---- softmax + write P (tf32, own cols) ----
        const float* mrow = sm + F_MSK + hw*32;
        #pragma unroll
        for (int j=0;j<4;++j){
            float2 mk = *(const float2*)(mrow + 8*j + 2*tig);
            float p0 = mk.x * __expf(s_[j][0]*SCALEF);
            float p1 = mk.y * __expf(s_[j][1]*SCALEF);
            float p2 = mk.x * __expf(s_[j][2]*SCALEF);
            float p3 = mk.y * __expf(s_[j][3]*SCALEF);
            lsum0 += p0 + p1;
            lsum1 += p2 + p3;
            uint2 uA = { f2t(p0), f2t(p1) };
            uint2 uB = { f2t(p2), f2t(p3) };
            int col = 8*(4*hw+j) + 2*tig;
            *(uint2*)(usm + F_P + rA*ST_P + col) = uA;
            *(uint2*)(usm + F_P + rB*ST_P + col) = uB;
        }

        // ---- prefetch next K/V + mask (covered by PV below) ----
        if (kt + 1 < NT){
            const float4* Kg4 = (const float4*)(Kg + (size_t)(kt+1)*BK*DH);
            const float4* Vg4 = (const float4*)(Vg + (size_t)(kt+1)*BK*DH);
            #pragma unroll
            for (int p=0;p<4;++p){ kreg[p]=Kg4[tid+p*256]; vreg[p]=Vg4[tid+p*256]; }
            mreg = (tid < BK) ? Mg[(kt+1)*BK + tid] : 0;
        }

        // ---- O += P V : this warp's 4 sk-chunks (k rows 32*hw .. +31) ----
        #pragma unroll
        for (int sk=0;sk<4;++sk){
            int skp = 4*hw + sk;
            uint32_t pa[4];
            const uint32_t* pb = usm + F_P + rA*ST_P + 8*skp + tig;
            pa[0]=pb[0]; pa[1]=pb[8*ST_P]; pa[2]=pb[4]; pa[3]=pb[8*ST_P+4];
            #pragma unroll
            for (int jd=0;jd<8;++jd){
                const uint32_t* vb = usm + F_VS + (8*skp+tig)*ST_V + 8*jd + gid;
                mma8(o[jd], pa, vb[0], vb[4*ST_V]);
            }
        }
    }

    // ---- epilogue: combine warp pairs ----
    lsum0 += __shfl_xor_sync(0xffffffffu, lsum0, 1);
    lsum0 += __shfl_xor_sync(0xffffffffu, lsum0, 2);
    lsum1 += __shfl_xor_sync(0xffffffffu, lsum1, 1);
    lsum1 += __shfl_xor_sync(0xffffffffu, lsum1, 2);

    __syncthreads();   // all PV reads of P done before scratch overwrite
    if (tig == 0){
        sm[F_LSB + hw*64 + wg*16 + gid]     = lsum0;
        sm[F_LSB + hw*64 + wg*16 + gid + 8] = lsum1;
    }
    if (hw == 1){
        #pragma unroll
        for (int jd=0;jd<8;++jd){
            float2 a = make_float2(o[jd][0], o[jd][1]);
            float2 c = make_float2(o[jd][2], o[jd][3]);
            *(float2*)(sm + F_P + rA*ST_P + 8*jd + 2*tig) = a;
            *(float2*)(sm + F_P + rB*ST_P + 8*jd + 2*tig) = c;
        }
    }
    __syncthreads();
    if (hw == 0){
        float inv0 = 1.f / (sm[F_LSB + wg*16 + gid]     + sm[F_LSB + 64 + wg*16 + gid]);
        float inv1 = 1.f / (sm[F_LSB + wg*16 + gid + 8] + sm[F_LSB + 64 + wg*16 + gid + 8]);
        #pragma unroll
        for (int jd=0;jd<8;++jd){
            float2 pA = *(const float2*)(sm + F_P + rA*ST_P + 8*jd + 2*tig);
            float2 pB = *(const float2*)(sm + F_P + rB*ST_P + 8*jd + 2*tig);
            float2 w0 = make_float2((o[jd][0]+pA.x)*inv0, (o[jd][1]+pA.y)*inv0);
            float2 w1 = make_float2((o[jd][2]+pB.x)*inv1, (o[jd][3]+pB.y)*inv1);
            *(float2*)(Og + (size_t)rA*DH + 8*jd + 2*tig) = w0;
            *(float2*)(Og + (size_t)rB*DH + 8*jd + 2*tig) = w1;
        }
    }
}

extern "C" void kernel_launch(void* const* d_in, const int* in_sizes, int n_in,
                              void* d_out, int out_size)
{
    const float* q = (const float*)d_in[0];
    const float* k = (const float*)d_in[1];
    const float* v = (const float*)d_in[2];
    const int*   m = (const int*)d_in[3];
    float* out = (float*)d_out;

    cudaFuncSetAttribute(attn_mma4_kernel,
                         cudaFuncAttributeMaxDynamicSharedMemorySize, SMEM_BYTES);

    dim3 grid(SEQ / BQ, 32);   // 32 q-tiles x (2 batch * 16 heads)
    dim3 block(256);
    attn_mma4_kernel<<<grid, block, SMEM_BYTES>>>(q, k, v, m, out);
}

// round 16
// speedup vs baseline: 1.3088x; 1.3088x over previous
#include <cuda_runtime.h>
#include <cstdint>
#include <math.h>

#define SEQ 2048
#define DH  64
#define BQ  128
#define BK  32
#define NT  (SEQ/BK)
#define SCALEF 0.03125f

#define ST_Q 68
#define ST_P 36
#define ST_K 68
#define ST_V 72

// smem float offsets
#define F_MSK 0                       // 32 (per-tile mask)
#define F_QS  32                      // 128 x 68
#define F_P   (F_QS + BQ*ST_Q)       // 8736: 128 x 36
#define F_KS  (F_P  + BQ*ST_P)       // 13344: 32 x 68
#define F_VS  (F_KS + BK*ST_K)       // 15520: 32 x 72
#define SMEM_FLOATS (F_VS + BK*ST_V) // 17824
#define SMEM_BYTES  (SMEM_FLOATS*4)  // 71296 -> 3 CTAs/SM

static __device__ __forceinline__ uint32_t f2t(float x){
    uint32_t r; asm("cvt.rna.tf32.f32 %0, %1;" : "=r"(r) : "f"(x)); return r;
}
static __device__ __forceinline__ void mma8(float c[4], const uint32_t a[4],
                                            uint32_t b0, uint32_t b1){
    asm volatile("mma.sync.aligned.m16n8k8.row.col.f32.tf32.tf32.f32 "
        "{%0,%1,%2,%3}, {%4,%5,%6,%7}, {%8,%9}, {%0,%1,%2,%3};"
        : "+f"(c[0]),"+f"(c[1]),"+f"(c[2]),"+f"(c[3])
        : "r"(a[0]),"r"(a[1]),"r"(a[2]),"r"(a[3]), "r"(b0),"r"(b1));
}

__global__ __launch_bounds__(256,3)
void attn_mma5_kernel(const float* __restrict__ Q, const float* __restrict__ K,
                      const float* __restrict__ V, const int* __restrict__ mask,
                      float* __restrict__ O)
{
    extern __shared__ float sm[];
    uint32_t* usm = (uint32_t*)sm;
    const int tid  = threadIdx.x;
    const int wid  = tid >> 5, lane = tid & 31;
    const int gid  = lane >> 2, tig = lane & 3;
    const int rA   = (wid << 4) + gid, rB = rA + 8;

    const int qt = blockIdx.x, bh = blockIdx.y, b = bh >> 4;
    const float* Qg = Q + ((size_t)bh*SEQ + (size_t)qt*BQ)*DH;
    const float* Kg = K + (size_t)bh*SEQ*DH;
    const float* Vg = V + (size_t)bh*SEQ*DH;
    const int*   Mg = mask + (size_t)b*SEQ;
    float*       Og = O + ((size_t)bh*SEQ + (size_t)qt*BQ)*DH;

    // ---- stage Q as tf32, row-major stride 68, STS.128 ----
    {
        const float4* Qg4 = (const float4*)Qg;
        #pragma unroll
        for (int p = 0; p < 8; ++p){
            int f = tid + p*256;
            float4 q4 = Qg4[f];
            int row = f >> 4, c4 = (f & 15) * 4;
            uint4 u = { f2t(q4.x), f2t(q4.y), f2t(q4.z), f2t(q4.w) };
            *(uint4*)(usm + F_QS + row*ST_Q + c4) = u;
        }
    }

    // ---- prefetch tile 0 K/V + mask ----
    float4 kreg[2], vreg[2];
    int mreg;
    {
        const float4* Kg4 = (const float4*)Kg;
        const float4* Vg4 = (const float4*)Vg;
        #pragma unroll
        for (int p=0;p<2;++p){ kreg[p]=Kg4[tid+p*256]; vreg[p]=Vg4[tid+p*256]; }
        mreg = (tid < BK) ? Mg[tid] : 0;
    }

    float o[8][4];
    float lsum0 = 0.f, lsum1 = 0.f;
    #pragma unroll
    for (int j=0;j<8;++j){ o[j][0]=o[j][1]=o[j][2]=o[j][3]=0.f; }

    for (int kt = 0; kt < NT; ++kt){
        if (kt) __syncthreads();    // prev PV done reading Ks/Vs/P; softmax done with msk

        // ---- stage K (stride 68) / V (stride 72) / mask ----
        #pragma unroll
        for (int p=0;p<2;++p){
            int f = tid + p*256;
            int row = f >> 4, c4 = (f & 15) * 4;
            uint4 ku = { f2t(kreg[p].x), f2t(kreg[p].y), f2t(kreg[p].z), f2t(kreg[p].w) };
            uint4 vu = { f2t(vreg[p].x), f2t(vreg[p].y), f2t(vreg[p].z), f2t(vreg[p].w) };
            *(uint4*)(usm + F_KS + row*ST_K + c4) = ku;
            *(uint4*)(usm + F_VS + row*ST_V + c4) = vu;
        }
        if (tid < BK) sm[F_MSK + tid] = (float)mreg;
        __syncthreads();

        // ---- S = Q K^T : 8 s-steps x 4 j-tiles ----
        float s_[4][4];
        #pragma unroll
        for (int j=0;j<4;++j){ s_[j][0]=s_[j][1]=s_[j][2]=s_[j][3]=0.f; }
        #pragma unroll
        for (int s=0;s<8;++s){
            uint32_t qa[4];
            const uint32_t* qb = usm + F_QS + rA*ST_Q + 8*s + tig;
            qa[0]=qb[0]; qa[1]=qb[8*ST_Q]; qa[2]=qb[4]; qa[3]=qb[8*ST_Q+4];
            #pragma unroll
            for (int j=0;j<4;++j){
                const uint32_t* kb = usm + F_KS + (8*j+gid)*ST_K + 8*s + tig;
                mma8(s_[j], qa, kb[0], kb[4]);
            }
        }

        // ---- softmax + write P (tf32, stride 36) ----
        #pragma unroll
        for (int j=0;j<4;++j){
            float2 mk = *(const float2*)(sm + F_MSK + 8*j + 2*tig);
            float p0 = mk.x * __expf(s_[j][0]*SCALEF);
            float p1 = mk.y * __expf(s_[j][1]*SCALEF);
            float p2 = mk.x * __expf(s_[j][2]*SCALEF);
            float p3 = mk.y * __expf(s_[j][3]*SCALEF);
            lsum0 += p0 + p1;
            lsum1 += p2 + p3;
            uint2 uA = { f2t(p0), f2t(p1) };
            uint2 uB = { f2t(p2), f2t(p3) };
            *(uint2*)(usm + F_P + rA*ST_P + 8*j + 2*tig) = uA;
            *(uint2*)(usm + F_P + rB*ST_P + 8*j + 2*tig) = uB;
        }

        // ---- prefetch next K/V + mask (covered by PV below) ----
        if (kt + 1 < NT){
            const float4* Kg4 = (const float4*)(Kg + (size_t)(kt+1)*BK*DH);
            const float4* Vg4 = (const float4*)(Vg + (size_t)(kt+1)*BK*DH);
            #pragma unroll
            for (int p=0;p<2;++p){ kreg[p]=Kg4[tid+p*256]; vreg[p]=Vg4[tid+p*256]; }
            mreg = (tid < BK) ? Mg[(kt+1)*BK + tid] : 0;
        }

        // ---- O += P V : 4 sk-chunks x 8 d-tiles ----
        #pragma unroll
        for (int sk=0;sk<4;++sk){
            uint32_t pa[4];
            const uint32_t* pb = usm + F_P + rA*ST_P + 8*sk + tig;
            pa[0]=pb[0]; pa[1]=pb[8*ST_P]; pa[2]=pb[4]; pa[3]=pb[8*ST_P+4];
            #pragma unroll
            for (int jd=0;jd<8;++jd){
                const uint32_t* vb = usm + F_VS + (8*sk+tig)*ST_V + 8*jd + gid;
                mma8(o[jd], pa, vb[0], vb[4*ST_V]);
            }
        }
    }

    // ---- epilogue ----
    lsum0 += __shfl_xor_sync(0xffffffffu, lsum0, 1);
    lsum0 += __shfl_xor_sync(0xffffffffu, lsum0, 2);
    lsum1 += __shfl_xor_sync(0xffffffffu, lsum1, 1);
    lsum1 += __shfl_xor_sync(0xffffffffu, lsum1, 2);
    float inv0 = 1.f / lsum0, inv1 = 1.f / lsum1;

    #pragma unroll
    for (int jd=0;jd<8;++jd){
        float2 w0 = make_float2(o[jd][0]*inv0, o[jd][1]*inv0);
        float2 w1 = make_float2(o[jd][2]*inv1, o[jd][3]*inv1);
        *(float2*)(Og + (size_t)rA*DH + 8*jd + 2*tig) = w0;
        *(float2*)(Og + (size_t)rB*DH + 8*jd + 2*tig) = w1;
    }
}

extern "C" void kernel_launch(void* const* d_in, const int* in_sizes, int n_in,
                              void* d_out, int out_size)
{
    const float* q = (const float*)d_in[0];
    const float* k = (const float*)d_in[1];
    const float* v = (const float*)d_in[2];
    const int*   m = (const int*)d_in[3];
    float* out = (float*)d_out;

    cudaFuncSetAttribute(attn_mma5_kernel,
                         cudaFuncAttributeMaxDynamicSharedMemorySize, SMEM_BYTES);

    dim3 grid(SEQ / BQ, 32);   // 16 q-tiles x (2 batch * 16 heads)
    dim3 block(256);
    attn_mma5_kernel<<<grid, block, SMEM_BYTES>>>(q, k, v, m, out);
}

// round 17
// speedup vs baseline: 1.7353x; 1.3258x over previous
#include <cuda_runtime.h>
#include <cstdint>
#include <math.h>

#define SEQ 2048
#define DH  64
#define BQ  128
#define BK  64
#define NT  (SEQ/BK)
#define SCALEF 0.03125f

#define ST_Q 68
#define ST_P 68
#define ST_K 68
#define ST_V 72

// smem float offsets (identical footprint to R12 best)
#define F_MSK 0
#define F_QS  2048
#define F_P   (F_QS + BQ*ST_Q)          // also epilogue lsum scratch
#define F_KS  (F_P  + BQ*ST_P)
#define F_VS  (F_KS + BK*ST_K)
#define SMEM_FLOATS (F_VS + BK*ST_V)
#define SMEM_BYTES  (SMEM_FLOATS*4)     // 113664 -> 2 CTAs/SM

static __device__ __forceinline__ uint32_t f2t(float x){
    uint32_t r; asm("cvt.rna.tf32.f32 %0, %1;" : "=r"(r) : "f"(x)); return r;
}
static __device__ __forceinline__ void mma8(float c[4], const uint32_t a[4],
                                            uint32_t b0, uint32_t b1){
    asm volatile("mma.sync.aligned.m16n8k8.row.col.f32.tf32.tf32.f32 "
        "{%0,%1,%2,%3}, {%4,%5,%6,%7}, {%8,%9}, {%0,%1,%2,%3};"
        : "+f"(c[0]),"+f"(c[1]),"+f"(c[2]),"+f"(c[3])
        : "r"(a[0]),"r"(a[1]),"r"(a[2]),"r"(a[3]), "r"(b0),"r"(b1));
}

__global__ __launch_bounds__(256,2)
void attn_mma6_kernel(const float* __restrict__ Q, const float* __restrict__ K,
                      const float* __restrict__ V, const int* __restrict__ mask,
                      float* __restrict__ O)
{
    extern __shared__ float sm[];
    uint32_t* usm = (uint32_t*)sm;
    const int tid  = threadIdx.x;
    const int wid  = tid >> 5, lane = tid & 31;
    const int gid  = lane >> 2, tig = lane & 3;
    const int rblk = wid & 3;              // 32-row block
    const int half = wid >> 2;             // col/d half (0: 0-31, 1: 32-63)
    const int r0   = rblk*32 + gid;        // rows r0, r0+8, r0+16, r0+24

    const int qt = blockIdx.x, bh = blockIdx.y, b = bh >> 4;
    const float* Qg = Q + ((size_t)bh*SEQ + (size_t)qt*BQ)*DH;
    const float* Kg = K + (size_t)bh*SEQ*DH;
    const float* Vg = V + (size_t)bh*SEQ*DH;
    const int*   Mg = mask + (size_t)b*SEQ;
    float*       Og = O + ((size_t)bh*SEQ + (size_t)qt*BQ)*DH;

    // ---- preload mask row as float (once) ----
    #pragma unroll
    for (int i = tid; i < SEQ; i += 256) sm[F_MSK + i] = (float)Mg[i];

    // ---- stage Q as tf32, row-major stride 68, STS.128 ----
    {
        const float4* Qg4 = (const float4*)Qg;
        #pragma unroll
        for (int p = 0; p < 8; ++p){
            int f = tid + p*256;
            float4 q4 = Qg4[f];
            int row = f >> 4, c4 = (f & 15) * 4;
            uint4 u = { f2t(q4.x), f2t(q4.y), f2t(q4.z), f2t(q4.w) };
            *(uint4*)(usm + F_QS + row*ST_Q + c4) = u;
        }
    }

    // ---- prefetch tile 0 K/V ----
    float4 kreg[4], vreg[4];
    {
        const float4* Kg4 = (const float4*)Kg;
        const float4* Vg4 = (const float4*)Vg;
        #pragma unroll
        for (int p=0;p<4;++p){ kreg[p]=Kg4[tid+p*256]; vreg[p]=Vg4[tid+p*256]; }
    }

    // o[rs][jd][4]: rows {r0+16rs, r0+8+16rs}, d-cols half*32+8jd+{2tig,2tig+1}
    float o[2][4][4];
    float lsum[2][2];   // [rs][row-within-pair]: cols of own half summed
    lsum[0][0]=lsum[0][1]=lsum[1][0]=lsum[1][1]=0.f;
    #pragma unroll
    for (int rs=0;rs<2;++rs)
        #pragma unroll
        for (int j=0;j<4;++j){ o[rs][j][0]=o[rs][j][1]=o[rs][j][2]=o[rs][j][3]=0.f; }

    for (int kt = 0; kt < NT; ++kt){
        if (kt) __syncthreads();    // prev PV done reading Ks/Vs/P

        // ---- stage K (stride 68) / V (stride 72), STS.128 ----
        #pragma unroll
        for (int p=0;p<4;++p){
            int f = tid + p*256;
            int row = f >> 4, c4 = (f & 15) * 4;
            uint4 ku = { f2t(kreg[p].x), f2t(kreg[p].y), f2t(kreg[p].z), f2t(kreg[p].w) };
            uint4 vu = { f2t(vreg[p].x), f2t(vreg[p].y), f2t(vreg[p].z), f2t(vreg[p].w) };
            *(uint4*)(usm + F_KS + row*ST_K + c4) = ku;
            *(uint4*)(usm + F_VS + row*ST_V + c4) = vu;
        }
        __syncthreads();

        // ---- S = Q K^T : warp tile 32x32; kb reused across 2 row-sets ----
        float s_[2][4][4];
        #pragma unroll
        for (int rs=0;rs<2;++rs)
            #pragma unroll
            for (int j=0;j<4;++j){ s_[rs][j][0]=s_[rs][j][1]=s_[rs][j][2]=s_[rs][j][3]=0.f; }
        #pragma unroll
        for (int s=0;s<8;++s){
            uint32_t qa[2][4];
            #pragma unroll
            for (int rs=0;rs<2;++rs){
                const uint32_t* qb = usm + F_QS + (r0 + 16*rs)*ST_Q + 8*s + tig;
                qa[rs][0]=qb[0]; qa[rs][1]=qb[8*ST_Q]; qa[rs][2]=qb[4]; qa[rs][3]=qb[8*ST_Q+4];
            }
            #pragma unroll
            for (int j=0;j<4;++j){
                const uint32_t* kb = usm + F_KS + (8*(4*half+j)+gid)*ST_K + 8*s + tig;
                uint32_t b0 = kb[0], b1 = kb[4];
                mma8(s_[0][j], qa[0], b0, b1);
                mma8(s_[1][j], qa[1], b0, b1);
            }
        }

        // ---- softmax + write P (own 32 cols, 4 rows/thread) ----
        const float* mrow = sm + F_MSK + kt*BK + half*32;
        #pragma unroll
        for (int rs=0;rs<2;++rs){
            #pragma unroll
            for (int j=0;j<4;++j){
                float2 mk = *(const float2*)(mrow + 8*j + 2*tig);
                float p0 = mk.x * __expf(s_[rs][j][0]*SCALEF);
                float p1 = mk.y * __expf(s_[rs][j][1]*SCALEF);
                float p2 = mk.x * __expf(s_[rs][j][2]*SCALEF);
                float p3 = mk.y * __expf(s_[rs][j][3]*SCALEF);
                lsum[rs][0] += p0 + p1;
                lsum[rs][1] += p2 + p3;
                uint2 uA = { f2t(p0), f2t(p1) };
                uint2 uB = { f2t(p2), f2t(p3) };
                int col = half*32 + 8*j + 2*tig;
                *(uint2*)(usm + F_P + (r0 + 16*rs)*ST_P + col) = uA;
                *(uint2*)(usm + F_P + (r0 + 8 + 16*rs)*ST_P + col) = uB;
            }
        }

        // ---- prefetch next K/V (issues LDGs before the sync) ----
        if (kt + 1 < NT){
            const float4* Kg4 = (const float4*)(Kg + (size_t)(kt+1)*BK*DH);
            const float4* Vg4 = (const float4*)(Vg + (size_t)(kt+1)*BK*DH);
            #pragma unroll
            for (int p=0;p<4;++p){ kreg[p]=Kg4[tid+p*256]; vreg[p]=Vg4[tid+p*256]; }
        }
        __syncthreads();   // P complete (PV reads both halves' columns)

        // ---- O += P V : warp tile 32 rows x 32 d; vb reused across 2 row-sets ----
        #pragma unroll
        for (int sk=0;sk<8;++sk){
            uint32_t pa[2][4];
            #pragma unroll
            for (int rs=0;rs<2;++rs){
                const uint32_t* pb = usm + F_P + (r0 + 16*rs)*ST_P + 8*sk + tig;
                pa[rs][0]=pb[0]; pa[rs][1]=pb[8*ST_P]; pa[rs][2]=pb[4]; pa[rs][3]=pb[8*ST_P+4];
            }
            #pragma unroll
            for (int jd=0;jd<4;++jd){
                const uint32_t* vb = usm + F_VS + (8*sk+tig)*ST_V + 8*(4*half+jd) + gid;
                uint32_t b0 = vb[0], b1 = vb[4*ST_V];
                mma8(o[0][jd], pa[0], b0, b1);
                mma8(o[1][jd], pa[1], b0, b1);
            }
        }
    }

    // ---- epilogue: combine lsum halves via retired P buffer ----
    #pragma unroll
    for (int rs=0;rs<2;++rs){
        #pragma unroll
        for (int c=0;c<2;++c){
            lsum[rs][c] += __shfl_xor_sync(0xffffffffu, lsum[rs][c], 1);
            lsum[rs][c] += __shfl_xor_sync(0xffffffffu, lsum[rs][c], 2);
        }
    }
    __syncthreads();   // final PV done reading P
    if (tig == 0){
        #pragma unroll
        for (int rs=0;rs<2;++rs){
            sm[F_P + half*128 + r0 + 16*rs]     = lsum[rs][0];
            sm[F_P + half*128 + r0 + 8 + 16*rs] = lsum[rs][1];
        }
    }
    __syncthreads();

    #pragma unroll
    for (int rs=0;rs<2;++rs){
        int ra = r0 + 16*rs, rb = ra + 8;
        float inva = 1.f / (sm[F_P + ra] + sm[F_P + 128 + ra]);
        float invb = 1.f / (sm[F_P + rb] + sm[F_P + 128 + rb]);
        #pragma unroll
        for (int jd=0;jd<4;++jd){
            int col = half*32 + 8*jd + 2*tig;
            float2 w0 = make_float2(o[rs][jd][0]*inva, o[rs][jd][1]*inva);
            float2 w1 = make_float2(o[rs][jd][2]*invb, o[rs][jd][3]*invb);
            *(float2*)(Og + (size_t)ra*DH + col) = w0;
            *(float2*)(Og + (size_t)rb*DH + col) = w1;
        }
    }
}

extern "C" void kernel_launch(void* const* d_in, const int* in_sizes, int n_in,
                              void* d_out, int out_size)
{
    const float* q = (const float*)d_in[0];
    const float* k = (const float*)d_in[1];
    const float* v = (const float*)d_in[2];
    const int*   m = (const int*)d_in[3];
    float* out = (float*)d_out;

    cudaFuncSetAttribute(attn_mma6_kernel,
                         cudaFuncAttributeMaxDynamicSharedMemorySize, SMEM_BYTES);

    dim3 grid(SEQ / BQ, 32);
    dim3 block(256);
    attn_mma6_kernel<<<grid, block, SMEM_BYTES>>>(q, k, v, m, out);
}